// round 3
// baseline (speedup 1.0000x reference)
#include <cuda_runtime.h>

#define NN 100000
#define EE 1600000
#define SCAN_NB 98   /* ceil(NN/1024) */

// ---------------- scratch (device globals; allocation-free) ----------------
__device__ int   g_deg_out[NN];      // zero-init; re-zeroed by k_norms each call
__device__ int   g_deg_in[NN];       // zero-init; re-zeroed by k_norms each call
__device__ int   g_scanS[NN];
__device__ int   g_blocksums[SCAN_NB];
__device__ int   g_blockoff[SCAN_NB];
__device__ int   g_rowptr[NN + 1];
__device__ int   g_cursor[NN];
__device__ int   g_csr[EE];
__device__ float g_ns[NN];
__device__ float g_nd[NN];
__device__ float g_xs [NN * 64];
__device__ float g_agg[NN * 64];
__device__ float g_hs [NN * 64];
__device__ float g_h2 [2][NN * 64];
__device__ float g_y  [NN * 64];
__device__ float g_red[128];         // zero-init; re-zeroed by finalize kernels
__device__ float g_mu  [2][64];
__device__ float g_istd[2][64];
__device__ float g_bnA[64];
__device__ float g_bnB[64];

// ---------------- degree histogram ----------------
__global__ void k_hist(const int* __restrict__ src, const int* __restrict__ dst) {
    int i = blockIdx.x * blockDim.x + threadIdx.x;
    if (i < EE) {
        atomicAdd(&g_deg_out[src[i]], 1);
        atomicAdd(&g_deg_in [dst[i]], 1);
    }
}

// ---------------- exclusive scan of deg_in -> rowptr/cursor ----------------
__global__ void k_scan1() {
    __shared__ int sm[256];
    int base = blockIdx.x * 1024 + threadIdx.x * 4;
    int v[4]; int s = 0;
#pragma unroll
    for (int t = 0; t < 4; t++) {
        v[t] = (base + t < NN) ? g_deg_in[base + t] : 0;
        s += v[t];
    }
    sm[threadIdx.x] = s;
    __syncthreads();
    for (int off = 1; off < 256; off <<= 1) {
        int add = (threadIdx.x >= off) ? sm[threadIdx.x - off] : 0;
        __syncthreads();
        sm[threadIdx.x] += add;
        __syncthreads();
    }
    int run = sm[threadIdx.x] - s;   // exclusive prefix for this thread
#pragma unroll
    for (int t = 0; t < 4; t++) {
        run += v[t];
        if (base + t < NN) g_scanS[base + t] = run;   // inclusive within block
    }
    if (threadIdx.x == 255) g_blocksums[blockIdx.x] = sm[255];
}

__global__ void k_scan2() {
    int acc = 0;
    for (int b = 0; b < SCAN_NB; b++) { g_blockoff[b] = acc; acc += g_blocksums[b]; }
}

__global__ void k_scan3() {
    int i = blockIdx.x * blockDim.x + threadIdx.x;
    if (i < NN) {
        int incl = g_scanS[i] + g_blockoff[i >> 10];
        int excl = incl - g_deg_in[i];
        g_rowptr[i] = excl;
        g_cursor[i] = excl;
        if (i == NN - 1) g_rowptr[NN] = incl;
    }
}

// ---------------- norms + consume/zero degrees ----------------
__global__ void k_norms() {
    int i = blockIdx.x * blockDim.x + threadIdx.x;
    if (i < NN) {
        float dout = (float)g_deg_out[i]; if (dout < 1.f) dout = 1.f;
        float din  = (float)g_deg_in [i]; if (din  < 1.f) din  = 1.f;
        g_ns[i] = rsqrtf(dout);
        g_nd[i] = rsqrtf(din);
        g_deg_out[i] = 0;
        g_deg_in [i] = 0;
    }
}

// ---------------- xs = feat * ns ----------------
__global__ void k_scalefeat(const float* __restrict__ feat) {
    int idx = blockIdx.x * blockDim.x + threadIdx.x;   // float4 index
    if (idx < NN * 16) {
        int node = idx >> 4;
        float s = g_ns[node];
        float4 v = ((const float4*)feat)[idx];
        v.x *= s; v.y *= s; v.z *= s; v.w *= s;
        ((float4*)g_xs)[idx] = v;
    }
}

// ---------------- CSR scatter (sort-by-dst via counting sort) ----------------
__global__ void k_scatter(const int* __restrict__ src, const int* __restrict__ dst) {
    int i = blockIdx.x * blockDim.x + threadIdx.x;
    if (i < EE) {
        int d = dst[i];
        int p = atomicAdd(&g_cursor[d], 1);
        g_csr[p] = src[i];
    }
}

// ---------------- gather SpMM: agg[d] = sum over in-edges of xsrc[s] ----------------
__global__ void __launch_bounds__(256) k_spmm(int in_sel) {
    const float* __restrict__ xsrc = (in_sel == 0) ? g_xs : g_hs;
    int t = blockIdx.x * blockDim.x + threadIdx.x;
    int node = t >> 4;
    int c = t & 15;
    if (node < NN) {
        int s0 = g_rowptr[node], s1 = g_rowptr[node + 1];
        int deg = s1 - s0;
        int half = deg >> 1;                 // paired iterations
        float4 accA = make_float4(0.f, 0.f, 0.f, 0.f);
        float4 accB = make_float4(0.f, 0.f, 0.f, 0.f);
        int j = s0;
        for (int it = 0; it < half; it++, j += 2) {
            int sA = __ldg(&g_csr[j]);
            int sB = __ldg(&g_csr[j + 1]);
            float4 vA = *(const float4*)(xsrc + sA * 64 + c * 4);
            float4 vB = *(const float4*)(xsrc + sB * 64 + c * 4);
            accA.x += vA.x; accA.y += vA.y; accA.z += vA.z; accA.w += vA.w;
            accB.x += vB.x; accB.y += vB.y; accB.z += vB.z; accB.w += vB.w;
        }
        if (deg & 1) {
            int sA = __ldg(&g_csr[j]);
            float4 vA = *(const float4*)(xsrc + sA * 64 + c * 4);
            accA.x += vA.x; accA.y += vA.y; accA.z += vA.z; accA.w += vA.w;
        }
        accA.x += accB.x; accA.y += accB.y; accA.z += accB.z; accA.w += accB.w;
        ((float4*)g_agg)[node * 16 + c] = accA;
    }
}

// ---------------- node GEMM: out = act(nd*agg @ W + b) [* ns] ----------------
__global__ void __launch_bounds__(128) k_gemm(const float* __restrict__ W,
                                              const float* __restrict__ bias,
                                              int out_sel, int relu, int post) {
    __shared__ float sW[64 * 64];
    __shared__ float sa[16][65];
    float* out = (out_sel == 0) ? g_hs : ((out_sel == 1) ? g_h2[0] : g_h2[1]);
    int tid = threadIdx.x;
    for (int idx = tid; idx < 1024; idx += 128)
        ((float4*)sW)[idx] = ((const float4*)W)[idx];
    int cg = tid & 15, ng = tid >> 4;
    float4 b4 = ((const float4*)bias)[cg];
    int blockbase = blockIdx.x * 64;
    for (int ch = 0; ch < 4; ch++) {
        int cb = blockbase + ch * 16;
        __syncthreads();
        for (int idx = tid; idx < 1024; idx += 128) {
            int n = idx >> 6, k = idx & 63;
            int gn = cb + n;
            float v = 0.f;
            if (gn < NN) v = g_agg[gn * 64 + k] * g_nd[gn];
            sa[n][k] = v;
        }
        __syncthreads();
        float4 A0 = make_float4(0.f, 0.f, 0.f, 0.f);
        float4 A1 = make_float4(0.f, 0.f, 0.f, 0.f);
#pragma unroll
        for (int k = 0; k < 64; k++) {
            float4 w = *(const float4*)&sW[k * 64 + cg * 4];
            float a0 = sa[ng * 2][k];
            float a1 = sa[ng * 2 + 1][k];
            A0.x += a0 * w.x; A0.y += a0 * w.y; A0.z += a0 * w.z; A0.w += a0 * w.w;
            A1.x += a1 * w.x; A1.y += a1 * w.y; A1.z += a1 * w.z; A1.w += a1 * w.w;
        }
        int gn0 = cb + ng * 2, gn1 = gn0 + 1;
        A0.x += b4.x; A0.y += b4.y; A0.z += b4.z; A0.w += b4.w;
        A1.x += b4.x; A1.y += b4.y; A1.z += b4.z; A1.w += b4.w;
        if (relu) {
            A0.x = fmaxf(A0.x, 0.f); A0.y = fmaxf(A0.y, 0.f); A0.z = fmaxf(A0.z, 0.f); A0.w = fmaxf(A0.w, 0.f);
            A1.x = fmaxf(A1.x, 0.f); A1.y = fmaxf(A1.y, 0.f); A1.z = fmaxf(A1.z, 0.f); A1.w = fmaxf(A1.w, 0.f);
        }
        if (gn0 < NN) {
            if (post) { float s = g_ns[gn0]; A0.x *= s; A0.y *= s; A0.z *= s; A0.w *= s; }
            ((float4*)out)[gn0 * 16 + cg] = A0;
        }
        if (gn1 < NN) {
            if (post) { float s = g_ns[gn1]; A1.x *= s; A1.y *= s; A1.z *= s; A1.w *= s; }
            ((float4*)out)[gn1 * 16 + cg] = A1;
        }
    }
}

// ---------------- per-column sum / sumsq reduction ----------------
__global__ void __launch_bounds__(256) k_colreduce(int which) {
    const float* __restrict__ buf = (which == 0) ? g_h2[0] : ((which == 1) ? g_h2[1] : g_y);
    __shared__ float ss[256], sq[256];
    int col = threadIdx.x & 63;
    int rg = threadIdx.x >> 6;
    float s = 0.f, q = 0.f;
    for (int r = blockIdx.x * 4 + rg; r < NN; r += gridDim.x * 4) {
        float v = buf[r * 64 + col];
        s += v; q += v * v;
    }
    ss[threadIdx.x] = s; sq[threadIdx.x] = q;
    __syncthreads();
    if (threadIdx.x < 128) {
        ss[threadIdx.x] += ss[threadIdx.x + 128];
        sq[threadIdx.x] += sq[threadIdx.x + 128];
    }
    __syncthreads();
    if (threadIdx.x < 64) {
        atomicAdd(&g_red[col],      ss[threadIdx.x] + ss[threadIdx.x + 64]);
        atomicAdd(&g_red[64 + col], sq[threadIdx.x] + sq[threadIdx.x + 64]);
    }
}

// ---------------- finalize z-score stats (ddof=1), consume/zero g_red ----------------
__global__ void k_finstats(int g) {
    int c = threadIdx.x;
    float s = g_red[c], q = g_red[64 + c];
    g_red[c] = 0.f; g_red[64 + c] = 0.f;
    float mu = s / (float)NN;
    float var = (q - (float)NN * mu * mu) / (float)(NN - 1);
    g_mu[g][c] = mu;
    g_istd[g][c] = rsqrtf(var);
}

// ---------------- z1/z2 write + z = avg + y = z @ Wm1 + bm1 ----------------
__global__ void __launch_bounds__(128) k_zy(const float* __restrict__ Wm1,
                                            const float* __restrict__ bm1,
                                            float* __restrict__ out) {
    __shared__ float sW[64 * 64];
    __shared__ float sa[16][65];
    int tid = threadIdx.x;
    for (int idx = tid; idx < 1024; idx += 128)
        ((float4*)sW)[idx] = ((const float4*)Wm1)[idx];
    int cg = tid & 15, ng = tid >> 4;
    float4 b4 = ((const float4*)bm1)[cg];
    int blockbase = blockIdx.x * 64;
    for (int ch = 0; ch < 4; ch++) {
        int cb = blockbase + ch * 16;
        __syncthreads();
        for (int idx = tid; idx < 1024; idx += 128) {
            int n = idx >> 6, k = idx & 63;
            int gn = cb + n;
            float v = 0.f;
            if (gn < NN) {
                float z1 = (g_h2[0][gn * 64 + k] - g_mu[0][k]) * g_istd[0][k];
                float z2 = (g_h2[1][gn * 64 + k] - g_mu[1][k]) * g_istd[1][k];
                out[gn * 64 + k] = z1;
                out[NN * 64 + gn * 64 + k] = z2;
                v = 0.5f * (z1 + z2);
            }
            sa[n][k] = v;
        }
        __syncthreads();
        float4 A0 = make_float4(0.f, 0.f, 0.f, 0.f);
        float4 A1 = make_float4(0.f, 0.f, 0.f, 0.f);
#pragma unroll
        for (int k = 0; k < 64; k++) {
            float4 w = *(const float4*)&sW[k * 64 + cg * 4];
            float a0 = sa[ng * 2][k];
            float a1 = sa[ng * 2 + 1][k];
            A0.x += a0 * w.x; A0.y += a0 * w.y; A0.z += a0 * w.z; A0.w += a0 * w.w;
            A1.x += a1 * w.x; A1.y += a1 * w.y; A1.z += a1 * w.z; A1.w += a1 * w.w;
        }
        int gn0 = cb + ng * 2, gn1 = gn0 + 1;
        A0.x += b4.x; A0.y += b4.y; A0.z += b4.z; A0.w += b4.w;
        A1.x += b4.x; A1.y += b4.y; A1.z += b4.z; A1.w += b4.w;
        if (gn0 < NN) ((float4*)g_y)[gn0 * 16 + cg] = A0;
        if (gn1 < NN) ((float4*)g_y)[gn1 * 16 + cg] = A1;
    }
}

// ---------------- finalize BN (biased var), consume/zero g_red ----------------
__global__ void k_finbn(const float* __restrict__ gamma, const float* __restrict__ beta) {
    int c = threadIdx.x;
    float s = g_red[c], q = g_red[64 + c];
    g_red[c] = 0.f; g_red[64 + c] = 0.f;
    float mu = s / (float)NN;
    float var = q / (float)NN - mu * mu;
    float sc = gamma[c] * rsqrtf(var + 1e-5f);
    g_bnA[c] = sc;
    g_bnB[c] = beta[c] - mu * sc;
}

// ---------------- head: relu(BN(y)) @ Wm2 + bm2 ----------------
__global__ void __launch_bounds__(192) k_head(const float* __restrict__ W2,
                                              const float* __restrict__ b2,
                                              float* __restrict__ out) {
    __shared__ float sW2[64 * 48];
    __shared__ float st[32][65];
    __shared__ float sb[48];
    int tid = threadIdx.x;
    for (int idx = tid; idx < 64 * 12; idx += 192) {
        int k = idx / 12, c = idx % 12;
        float4 v = make_float4(0.f, 0.f, 0.f, 0.f);
        if (c < 10) v = *(const float4*)&W2[k * 40 + c * 4];
        ((float4*)sW2)[k * 12 + c] = v;
    }
    if (tid < 48) sb[tid] = (tid < 40) ? b2[tid] : 0.f;
    int cg = tid % 12, ng = tid / 12;   // 16 node groups x 2 nodes
    int blockbase = blockIdx.x * 64;
    for (int ch = 0; ch < 2; ch++) {
        int cb = blockbase + ch * 32;
        __syncthreads();
        for (int idx = tid; idx < 2048; idx += 192) {
            int n = idx >> 6, k = idx & 63;
            int gn = cb + n;
            float v = 0.f;
            if (gn < NN) {
                v = g_y[gn * 64 + k] * g_bnA[k] + g_bnB[k];
                v = fmaxf(v, 0.f);
            }
            st[n][k] = v;
        }
        __syncthreads();
        float4 A0 = make_float4(0.f, 0.f, 0.f, 0.f);
        float4 A1 = make_float4(0.f, 0.f, 0.f, 0.f);
#pragma unroll
        for (int k = 0; k < 64; k++) {
            float4 w = ((float4*)sW2)[k * 12 + cg];
            float a0 = st[ng * 2][k];
            float a1 = st[ng * 2 + 1][k];
            A0.x += a0 * w.x; A0.y += a0 * w.y; A0.z += a0 * w.z; A0.w += a0 * w.w;
            A1.x += a1 * w.x; A1.y += a1 * w.y; A1.z += a1 * w.z; A1.w += a1 * w.w;
        }
        int gn0 = cb + ng * 2, gn1 = gn0 + 1;
        float r0[4] = {A0.x + sb[cg * 4], A0.y + sb[cg * 4 + 1], A0.z + sb[cg * 4 + 2], A0.w + sb[cg * 4 + 3]};
        float r1[4] = {A1.x + sb[cg * 4], A1.y + sb[cg * 4 + 1], A1.z + sb[cg * 4 + 2], A1.w + sb[cg * 4 + 3]};
        float* pred = out + (size_t)NN * 128;
#pragma unroll
        for (int i = 0; i < 4; i++) {
            int col = cg * 4 + i;
            if (col < 40) {
                if (gn0 < NN) pred[gn0 * 40 + col] = r0[i];
                if (gn1 < NN) pred[gn1 * 40 + col] = r1[i];
            }
        }
    }
}

// ---------------- launch ----------------
extern "C" void kernel_launch(void* const* d_in, const int* in_sizes, int n_in,
                              void* d_out, int out_size) {
    const float* feat[2] = {(const float*)d_in[0], (const float*)d_in[3]};
    const int*   src [2] = {(const int*)d_in[1], (const int*)d_in[4]};
    const int*   dst [2] = {(const int*)d_in[2], (const int*)d_in[5]};
    const float* W1  [2] = {(const float*)d_in[6],  (const float*)d_in[10]};
    const float* B1  [2] = {(const float*)d_in[7],  (const float*)d_in[11]};
    const float* W2  [2] = {(const float*)d_in[8],  (const float*)d_in[12]};
    const float* B2  [2] = {(const float*)d_in[9],  (const float*)d_in[13]};
    const float* Wm1   = (const float*)d_in[14];
    const float* bm1   = (const float*)d_in[15];
    const float* gamma = (const float*)d_in[16];
    const float* beta  = (const float*)d_in[17];
    const float* Wm2   = (const float*)d_in[18];
    const float* bm2   = (const float*)d_in[19];
    float* out = (float*)d_out;

    const int EB = (EE + 255) / 256;        // 6250
    const int NB = (NN + 255) / 256;        // 391
    const int GB = (NN + 63) / 64;          // 1563

    for (int g = 0; g < 2; g++) {
        k_hist<<<EB, 256>>>(src[g], dst[g]);
        k_scan1<<<SCAN_NB, 256>>>();
        k_scan2<<<1, 1>>>();
        k_scan3<<<NB, 256>>>();
        k_norms<<<NB, 256>>>();
        k_scalefeat<<<(NN * 16 + 255) / 256, 256>>>(feat[g]);
        k_scatter<<<EB, 256>>>(src[g], dst[g]);
        k_spmm<<<(NN * 16 + 255) / 256, 256>>>(0);
        k_gemm<<<GB, 128>>>(W1[g], B1[g], 0, 1, 1);
        k_spmm<<<(NN * 16 + 255) / 256, 256>>>(1);
        k_gemm<<<GB, 128>>>(W2[g], B2[g], 1 + g, 0, 0);
        k_colreduce<<<512, 256>>>(g);
        k_finstats<<<1, 64>>>(g);
    }
    k_zy<<<GB, 128>>>(Wm1, bm1, out);
    k_colreduce<<<512, 256>>>(2);
    k_finbn<<<1, 64>>>(gamma, beta);
    k_head<<<GB, 192>>>(Wm2, bm2, out);
}